// round 10
// baseline (speedup 1.0000x reference)
#include <cuda_runtime.h>

#define NC 24
#define LH 256
#define LW 256
#define PLANE (LH*LW)
#define R 8
#define EPSF 1e-4f

// per-plane item layout: [0,64) hbox(4 rows) | [64,96) vbox(8 rows) | [96,224) apply(8 HR rows)
#define IT_H 64
#define IT_V 32
#define IT_A 128
#define ITEMS_PL (IT_H + IT_V + IT_A)     // 224
#define TOTAL_ITEMS (NC * ITEMS_PL)       // 5376
#define GRID_BLOCKS 740                   // ~one wave at 5 blocks/SM

// scratch (allocation-free rule: __device__ globals)
__device__ float4 g_h4[NC*PLANE];   // {hsumI, hsumP, hsumIP, hsumII}
__device__ float2 g_AB[NC*PLANE];   // {A, B}
__device__ int    g_item;
__device__ int    g_cnt_h[NC];
__device__ int    g_cnt_v[NC];

__global__ void k_reset()
{
    const int t = threadIdx.x;
    if (t < NC) { g_cnt_h[t] = 0; g_cnt_v[t] = 0; }
    if (t == NC) g_item = 0;
}

__device__ __forceinline__ float4 ldz(const float* __restrict__ row, int col)
{
    if (col < 0 || col >= LW) return make_float4(0.f, 0.f, 0.f, 0.f);
    return *reinterpret_cast<const float4*>(row + col);
}

// ---------------------------------------------------------------------------
// Persistent pipeline kernel: one wave of blocks pulls items off a global
// queue. Items are plane-major so every item's dependencies have smaller
// indices -> grabbed earlier -> progress guaranteed for any grid size.
// ---------------------------------------------------------------------------
__global__ void __launch_bounds__(256) k_pipe(
    const float* __restrict__ p, const float* __restrict__ I,
    const float* __restrict__ Ihr, float* __restrict__ out)
{
    __shared__ float2 sAB[4][LW];
    __shared__ int s_item;

    const int tid = threadIdx.x;

    for (;;) {
        __syncthreads();                   // protect smem reuse across items
        if (tid == 0) s_item = atomicAdd(&g_item, 1);
        __syncthreads();
        const int it = s_item;
        if (it >= TOTAL_ITEMS) return;

        const int pl = it / ITEMS_PL;
        const int r  = it - pl*ITEMS_PL;

        if (r < IT_H) {
            // --------------------------- hbox ------------------------------
            const int rr  = tid >> 6;              // 0..3
            const int tx  = tid & 63;
            const int row = r*4 + rr;
            const int gbase = pl*PLANE + row*LW;
            const int xb  = tx << 2;

            const float* __restrict__ Irow = I + gbase;
            const float* __restrict__ Prow = p + gbase;

            float4 i4[5], p4[5];
            #pragma unroll
            for (int j = 0; j < 5; j++) {
                const int col = xb - 8 + 4*j;
                i4[j] = ldz(Irow, col);
                p4[j] = ldz(Prow, col);
            }

            float iv[20], pv[20];
            #pragma unroll
            for (int j = 0; j < 5; j++) {
                iv[4*j+0] = i4[j].x; iv[4*j+1] = i4[j].y; iv[4*j+2] = i4[j].z; iv[4*j+3] = i4[j].w;
                pv[4*j+0] = p4[j].x; pv[4*j+1] = p4[j].y; pv[4*j+2] = p4[j].z; pv[4*j+3] = p4[j].w;
            }

            float sI = 0.f, sP = 0.f, sIP = 0.f, sII = 0.f;
            #pragma unroll
            for (int j = 0; j < 17; j++) {
                sI += iv[j]; sP += pv[j]; sIP += iv[j]*pv[j]; sII += iv[j]*iv[j];
            }

            float4* __restrict__ dst = g_h4 + gbase + xb;
            dst[0] = make_float4(sI, sP, sIP, sII);
            #pragma unroll
            for (int k = 1; k < 4; k++) {
                sI  += iv[16+k] - iv[k-1];
                sP  += pv[16+k] - pv[k-1];
                sIP += iv[16+k]*pv[16+k] - iv[k-1]*pv[k-1];
                sII += iv[16+k]*iv[16+k] - iv[k-1]*iv[k-1];
                dst[k] = make_float4(sI, sP, sIP, sII);
            }

            __threadfence();
            __syncthreads();
            if (tid == 0) atomicAdd(&g_cnt_h[pl], 1);

        } else if (r < IT_H + IT_V) {
            // --------------------------- vbox ------------------------------
            if (tid == 0) {
                while (atomicAdd(&g_cnt_h[pl], 0) < IT_H) __nanosleep(32);
            }
            __syncthreads();
            __threadfence();

            const int c  = tid;
            const int y0 = (r - IT_H) * 8;

            const float4* __restrict__ h = g_h4 + pl*PLANE + c;

            float sI = 0.f, sP = 0.f, sIP = 0.f, sII = 0.f;
            {
                const int lo = max(y0 - R, 0);
                const int hi = min(y0 + R, LH - 1);
                for (int yy = lo; yy <= hi; yy++) {
                    const float4 v = h[yy*LW];
                    sI += v.x; sP += v.y; sIP += v.z; sII += v.w;
                }
            }

            const float cx = (float)(min(c + R, LW-1) - max(c - R, 0) + 1);
            float2* __restrict__ ABp = g_AB + pl*PLANE + c;

            #pragma unroll
            for (int i = 0; i < 8; i++) {
                const int yo = y0 + i;
                const float cy  = (float)(min(yo + R, LH-1) - max(yo - R, 0) + 1);
                const float inv = 1.0f / (cx * cy);

                const float mI = sI*inv;
                const float mP = sP*inv;
                const float A  = (sIP*inv - mI*mP) / ((sII*inv - mI*mI) + EPSF);
                const float B  = mP - A*mI;

                ABp[yo*LW] = make_float2(A, B);

                const int ya = yo + R + 1;
                if (ya <= LH - 1) {
                    const float4 v = h[ya*LW];
                    sI += v.x; sP += v.y; sIP += v.z; sII += v.w;
                }
                const int ysub = yo - R;
                if (ysub >= 0) {
                    const float4 v = h[ysub*LW];
                    sI -= v.x; sP -= v.y; sIP -= v.z; sII -= v.w;
                }
            }

            __threadfence();
            __syncthreads();
            if (tid == 0) atomicAdd(&g_cnt_v[pl], 1);

        } else {
            // --------------------------- apply -----------------------------
            if (tid == 0) {
                while (atomicAdd(&g_cnt_v[pl], 0) < IT_V) __nanosleep(32);
            }
            __syncthreads();
            __threadfence();

            const int m  = r - (IT_H + IT_V);     // 0..127
            const int t  = tid;
            const int k0 = m << 1;

            const int r0 = max(k0 - 1, 0);
            const int r3 = min(k0 + 2, LH - 1);

            const float2* __restrict__ AB = g_AB + pl*PLANE;
            sAB[0][t] = AB[r0     *LW + t];
            sAB[1][t] = AB[ k0    *LW + t];
            sAB[2][t] = AB[(k0+1) *LW + t];
            sAB[3][t] = AB[r3     *LW + t];
            __syncthreads();

            const int xm = max(t - 1, 0);
            const int xp = min(t + 1, LW - 1);

            float xA[4][4], xB[4][4];
            #pragma unroll
            for (int j = 0; j < 4; j++) {
                const float2 vm = sAB[j][xm], v0 = sAB[j][t], vp = sAB[j][xp];
                xA[j][0] = 0.375f*vm.x + 0.625f*v0.x;  xB[j][0] = 0.375f*vm.y + 0.625f*v0.y;
                xA[j][1] = 0.125f*vm.x + 0.875f*v0.x;  xB[j][1] = 0.125f*vm.y + 0.875f*v0.y;
                xA[j][2] = 0.875f*v0.x + 0.125f*vp.x;  xB[j][2] = 0.875f*v0.y + 0.125f*vp.y;
                xA[j][3] = 0.625f*v0.x + 0.375f*vp.x;  xB[j][3] = 0.625f*v0.y + 0.375f*vp.y;
            }

            const int base = ((pl << 10) + (m << 3)) * 1024 + (t << 2);

            float4 ivv[8];
            #pragma unroll
            for (int i = 0; i < 8; i++)
                ivv[i] = __ldcs(reinterpret_cast<const float4*>(Ihr + base + i*1024));

#define OUTV(i, W0, J0, W1, J1)                                                 \
    {                                                                           \
        float4 ov;                                                              \
        ov.x = (W0*xA[J0][0] + W1*xA[J1][0])*ivv[i].x + (W0*xB[J0][0] + W1*xB[J1][0]); \
        ov.y = (W0*xA[J0][1] + W1*xA[J1][1])*ivv[i].y + (W0*xB[J0][1] + W1*xB[J1][1]); \
        ov.z = (W0*xA[J0][2] + W1*xA[J1][2])*ivv[i].z + (W0*xB[J0][2] + W1*xB[J1][2]); \
        ov.w = (W0*xA[J0][3] + W1*xA[J1][3])*ivv[i].w + (W0*xB[J0][3] + W1*xB[J1][3]); \
        __stcs(reinterpret_cast<float4*>(out + base + (i)*1024), ov);           \
    }
            OUTV(0, 0.375f, 0, 0.625f, 1)
            OUTV(1, 0.125f, 0, 0.875f, 1)
            OUTV(2, 0.875f, 1, 0.125f, 2)
            OUTV(3, 0.625f, 1, 0.375f, 2)
            OUTV(4, 0.375f, 1, 0.625f, 2)
            OUTV(5, 0.125f, 1, 0.875f, 2)
            OUTV(6, 0.875f, 2, 0.125f, 3)
            OUTV(7, 0.625f, 2, 0.375f, 3)
#undef OUTV
        }
    }
}

// ---------------------------------------------------------------------------
extern "C" void kernel_launch(void* const* d_in, const int* in_sizes, int n_in,
                              void* d_out, int out_size)
{
    const float* p_lr = (const float*)d_in[0];
    const float* I_lr = (const float*)d_in[1];
    const float* I_hr = (const float*)d_in[2];
    float* out = (float*)d_out;

    k_reset<<<1, 32>>>();
    k_pipe<<<GRID_BLOCKS, 256>>>(p_lr, I_lr, I_hr, out);
}

// round 11
// speedup vs baseline: 1.6194x; 1.6194x over previous
#include <cuda_runtime.h>

#define NC 24
#define LH 256
#define LW 256
#define PLANE (LH*LW)
#define R 8
#define EPSF 1e-4f

// scratch (allocation-free rule: __device__ globals)
__device__ float4 g_h4[NC*PLANE];   // {hsumI, hsumP, hsumIP, hsumII}

__device__ __forceinline__ float4 ldz(const float* __restrict__ row, int col)
{
    if (col < 0 || col >= LW) return make_float4(0.f, 0.f, 0.f, 0.f);
    return *reinterpret_cast<const float4*>(row + col);
}

// ---------------------------------------------------------------------------
// Kernel 1: horizontal truncated window sums of I, p, I*p, I*I.
// Truncated window == full 17-tap window over a zero-padded row.
// Each thread owns 4 columns of one row. Register-lean form: only the two
// boundary chunks stay live; mid chunks are consumed on arrival.
// Block = 256 threads = 4 rows x 64 col-groups. Grid = (64, NC).
// ---------------------------------------------------------------------------
__global__ void __launch_bounds__(256) k_hbox(
    const float* __restrict__ p, const float* __restrict__ I)
{
    const int tid = threadIdx.x;
    const int r   = tid >> 6;          // row in block 0..3
    const int tx  = tid & 63;
    const int row = blockIdx.x * 4 + r;
    const int pl  = blockIdx.y;
    const int gbase = pl*PLANE + row*LW;
    const int xb  = tx << 2;           // first output column

    const float* __restrict__ Irow = I + gbase;
    const float* __restrict__ Prow = p + gbase;

    // window for outputs xb..xb+3 spans columns [xb-8, xb+11]
    const float4 i0 = ldz(Irow, xb - 8);
    const float4 p0 = ldz(Prow, xb - 8);
    const float4 i4 = ldz(Irow, xb + 8);
    const float4 p4 = ldz(Prow, xb + 8);

    float sI = 0.f, sP = 0.f, sIP = 0.f, sII = 0.f;
    #pragma unroll
    for (int j = 1; j < 4; j++) {
        const float4 a = ldz(Irow, xb - 8 + 4*j);
        const float4 b = ldz(Prow, xb - 8 + 4*j);
        sI  += a.x + a.y + a.z + a.w;
        sP  += b.x + b.y + b.z + b.w;
        sIP += a.x*b.x + a.y*b.y + a.z*b.z + a.w*b.w;
        sII += a.x*a.x + a.y*a.y + a.z*a.z + a.w*a.w;
    }
    // boundary contributions for output 0 (taps 0..16)
    sI  += i0.x + i0.y + i0.z + i0.w + i4.x;
    sP  += p0.x + p0.y + p0.z + p0.w + p4.x;
    sIP += i0.x*p0.x + i0.y*p0.y + i0.z*p0.z + i0.w*p0.w + i4.x*p4.x;
    sII += i0.x*i0.x + i0.y*i0.y + i0.z*i0.z + i0.w*i0.w + i4.x*i4.x;

    float4* __restrict__ dst = g_h4 + gbase + xb;
    dst[0] = make_float4(sI, sP, sIP, sII);

    // slide: out k drops tap (k-1) = i0 comp, gains tap (16+k) = i4 comp
    sI  += i4.y - i0.x;  sP  += p4.y - p0.x;
    sIP += i4.y*p4.y - i0.x*p0.x;  sII += i4.y*i4.y - i0.x*i0.x;
    dst[1] = make_float4(sI, sP, sIP, sII);

    sI  += i4.z - i0.y;  sP  += p4.z - p0.y;
    sIP += i4.z*p4.z - i0.y*p0.y;  sII += i4.z*i4.z - i0.y*i0.y;
    dst[2] = make_float4(sI, sP, sIP, sII);

    sI  += i4.w - i0.z;  sP  += p4.w - p0.z;
    sIP += i4.w*p4.w - i0.z*p0.z;  sII += i4.w*i4.w - i0.z*i0.z;
    dst[3] = make_float4(sI, sP, sIP, sII);
}

// ---------------------------------------------------------------------------
// Kernel 2 (fused vbox+solve+upsample+apply):
// Block mb covers HR rows 32mb..32mb+31  (LR rows k0..k0+7, k0=8mb).
// Needs A,B for LR rows k0-1..k0+8 (clamped) -> computed in-block from g_h4
// via per-column vertical sliding window (L2-resident), stored to smem.
// Then x4 bilinear upsample + out = A*I_hr + B, 8 quads x 4 float4 per thread.
// Grid = (32, NC), 256 threads.
// ---------------------------------------------------------------------------
__global__ void __launch_bounds__(256) k_solve_apply(
    const float* __restrict__ Ihr, float* __restrict__ out)
{
    __shared__ float2 sAB[10][LW];

    const int mb = blockIdx.x;        // 0..31
    const int pl = blockIdx.y;
    const int t  = threadIdx.x;       // column
    const int k0 = mb << 3;

    // ---- vertical sliding window over g_h4 column t ----
    {
        const float4* __restrict__ h = g_h4 + pl*PLANE + t;
        const float cx = (float)(min(t + R, LW-1) - max(t - R, 0) + 1);

        int rcur = max(k0 - 1, 0);     // first A,B row to produce
        float sI = 0.f, sP = 0.f, sIP = 0.f, sII = 0.f;
        {
            const int lo = max(rcur - R, 0);
            const int hi = min(rcur + R, LH - 1);
            for (int yy = lo; yy <= hi; yy++) {
                const float4 v = h[yy*LW];
                sI += v.x; sP += v.y; sIP += v.z; sII += v.w;
            }
        }

        #pragma unroll
        for (int j = 0; j < 10; j++) {
            const int target = min(max(k0 - 1 + j, 0), LH - 1);
            if (target != rcur) {
                // slide rcur -> rcur+1
                const int ya = rcur + R + 1;
                if (ya <= LH - 1) {
                    const float4 v = h[ya*LW];
                    sI += v.x; sP += v.y; sIP += v.z; sII += v.w;
                }
                const int ys = rcur - R;
                if (ys >= 0) {
                    const float4 v = h[ys*LW];
                    sI -= v.x; sP -= v.y; sIP -= v.z; sII -= v.w;
                }
                rcur = target;
            }
            const float cy  = (float)(min(rcur + R, LH-1) - max(rcur - R, 0) + 1);
            const float inv = 1.0f / (cx * cy);
            const float mI = sI*inv;
            const float mP = sP*inv;
            const float A  = (sIP*inv - mI*mP) / ((sII*inv - mI*mI) + EPSF);
            sAB[j][t] = make_float2(A, mP - A*mI);
        }
    }
    __syncthreads();

    // ---- upsample + apply ----
    const int xm = max(t - 1, 0);
    const int xp = min(t + 1, LW - 1);
    const int base = ((pl << 10) + (mb << 5)) * 1024 + (t << 2);

    // quad i4 -> LR row k = k0+i4 -> smem rows i4 (k-1), i4+1 (k), i4+2 (k+1)
    #pragma unroll
    for (int i4 = 0; i4 < 8; i4++) {
        const float2 um = sAB[i4  ][xm], u0 = sAB[i4  ][t], up = sAB[i4  ][xp];
        const float2 vm = sAB[i4+1][xm], v0 = sAB[i4+1][t], vp = sAB[i4+1][xp];
        const float2 wm = sAB[i4+2][xm], w0 = sAB[i4+2][t], wp = sAB[i4+2][xp];

        // x-lerp for the 3 LR rows (4 fixed weights each)
        float uA[4], uB[4], vA[4], vB[4], wA[4], wB[4];
        uA[0] = 0.375f*um.x + 0.625f*u0.x;  uB[0] = 0.375f*um.y + 0.625f*u0.y;
        uA[1] = 0.125f*um.x + 0.875f*u0.x;  uB[1] = 0.125f*um.y + 0.875f*u0.y;
        uA[2] = 0.875f*u0.x + 0.125f*up.x;  uB[2] = 0.875f*u0.y + 0.125f*up.y;
        uA[3] = 0.625f*u0.x + 0.375f*up.x;  uB[3] = 0.625f*u0.y + 0.375f*up.y;
        vA[0] = 0.375f*vm.x + 0.625f*v0.x;  vB[0] = 0.375f*vm.y + 0.625f*v0.y;
        vA[1] = 0.125f*vm.x + 0.875f*v0.x;  vB[1] = 0.125f*vm.y + 0.875f*v0.y;
        vA[2] = 0.875f*v0.x + 0.125f*vp.x;  vB[2] = 0.875f*v0.y + 0.125f*vp.y;
        vA[3] = 0.625f*v0.x + 0.375f*vp.x;  vB[3] = 0.625f*v0.y + 0.375f*vp.y;
        wA[0] = 0.375f*wm.x + 0.625f*w0.x;  wB[0] = 0.375f*wm.y + 0.625f*w0.y;
        wA[1] = 0.125f*wm.x + 0.875f*w0.x;  wB[1] = 0.125f*wm.y + 0.875f*w0.y;
        wA[2] = 0.875f*w0.x + 0.125f*wp.x;  wB[2] = 0.875f*w0.y + 0.125f*wp.y;
        wA[3] = 0.625f*w0.x + 0.375f*wp.x;  wB[3] = 0.625f*w0.y + 0.375f*wp.y;

        const int qbase = base + (i4 << 2) * 1024;
        const float4 g0 = __ldcs(reinterpret_cast<const float4*>(Ihr + qbase));
        const float4 g1 = __ldcs(reinterpret_cast<const float4*>(Ihr + qbase + 1024));
        const float4 g2 = __ldcs(reinterpret_cast<const float4*>(Ihr + qbase + 2048));
        const float4 g3 = __ldcs(reinterpret_cast<const float4*>(Ihr + qbase + 3072));

        // HR sub-row q: q=0 rows(k-1,k) w(.375,.625); q=1 (.125,.875);
        //               q=2 rows(k,k+1) w(.875,.125); q=3 (.625,.375)
        float4 o0, o1, o2, o3;
        o0.x = (0.375f*uA[0]+0.625f*vA[0])*g0.x + (0.375f*uB[0]+0.625f*vB[0]);
        o0.y = (0.375f*uA[1]+0.625f*vA[1])*g0.y + (0.375f*uB[1]+0.625f*vB[1]);
        o0.z = (0.375f*uA[2]+0.625f*vA[2])*g0.z + (0.375f*uB[2]+0.625f*vB[2]);
        o0.w = (0.375f*uA[3]+0.625f*vA[3])*g0.w + (0.375f*uB[3]+0.625f*vB[3]);

        o1.x = (0.125f*uA[0]+0.875f*vA[0])*g1.x + (0.125f*uB[0]+0.875f*vB[0]);
        o1.y = (0.125f*uA[1]+0.875f*vA[1])*g1.y + (0.125f*uB[1]+0.875f*vB[1]);
        o1.z = (0.125f*uA[2]+0.875f*vA[2])*g1.z + (0.125f*uB[2]+0.875f*vB[2]);
        o1.w = (0.125f*uA[3]+0.875f*vA[3])*g1.w + (0.125f*uB[3]+0.875f*vB[3]);

        o2.x = (0.875f*vA[0]+0.125f*wA[0])*g2.x + (0.875f*vB[0]+0.125f*wB[0]);
        o2.y = (0.875f*vA[1]+0.125f*wA[1])*g2.y + (0.875f*vB[1]+0.125f*wB[1]);
        o2.z = (0.875f*vA[2]+0.125f*wA[2])*g2.z + (0.875f*vB[2]+0.125f*wB[2]);
        o2.w = (0.875f*vA[3]+0.125f*wA[3])*g2.w + (0.875f*vB[3]+0.125f*wB[3]);

        o3.x = (0.625f*vA[0]+0.375f*wA[0])*g3.x + (0.625f*vB[0]+0.375f*wB[0]);
        o3.y = (0.625f*vA[1]+0.375f*wA[1])*g3.y + (0.625f*vB[1]+0.375f*wB[1]);
        o3.z = (0.625f*vA[2]+0.375f*wA[2])*g3.z + (0.625f*vB[2]+0.375f*wB[2]);
        o3.w = (0.625f*vA[3]+0.375f*wA[3])*g3.w + (0.625f*vB[3]+0.375f*wB[3]);

        __stcs(reinterpret_cast<float4*>(out + qbase),        o0);
        __stcs(reinterpret_cast<float4*>(out + qbase + 1024), o1);
        __stcs(reinterpret_cast<float4*>(out + qbase + 2048), o2);
        __stcs(reinterpret_cast<float4*>(out + qbase + 3072), o3);
    }
}

// ---------------------------------------------------------------------------
extern "C" void kernel_launch(void* const* d_in, const int* in_sizes, int n_in,
                              void* d_out, int out_size)
{
    const float* p_lr = (const float*)d_in[0];
    const float* I_lr = (const float*)d_in[1];
    const float* I_hr = (const float*)d_in[2];
    float* out = (float*)d_out;

    k_hbox      <<<dim3(LH/4, NC), 256>>>(p_lr, I_lr);
    k_solve_apply<<<dim3(LH/8, NC), 256>>>(I_hr, out);
}

// round 12
// speedup vs baseline: 2.0793x; 1.2840x over previous
#include <cuda_runtime.h>

#define NC 24
#define LH 256
#define LW 256
#define PLANE (LH*LW)
#define R 8
#define EPSF 1e-4f
#define HSROW 272               // 8 zero-halo + 256 + 8 zero-halo
#define SMEM_BYTES (4*10*HSROW*4 + 10*LW*8)   // 43520 + 20480 = 64000

// ---------------------------------------------------------------------------
// Single fused kernel. Block mb covers HR rows 32mb..32mb+31 (LR rows
// k0..k0+7, k0=8mb). Grid = (32, NC), 256 threads.
//   Stage V: per-column vertical truncated sliding window over raw I,p
//            -> 10 vsum rows (stats I,P,IP,II) in zero-padded smem.
//   Stage H: horizontal 17-tap running-sum windows (conflict-free float4
//            chunks) + count division + A,B solve -> sAB smem.
//   Stage A: x4 bilinear upsample (half-pixel, edge-clamp == jax linear)
//            fused with out = A*I_hr + B. 8 quads x 4 float4 per thread.
// ---------------------------------------------------------------------------
__global__ void __launch_bounds__(256) k_gf(
    const float* __restrict__ p, const float* __restrict__ I,
    const float* __restrict__ Ihr, float* __restrict__ out)
{
    extern __shared__ float sm[];
    float*  vsI  = sm;                    // [10][HSROW]
    float*  vsP  = vsI  + 10*HSROW;
    float*  vsIP = vsP  + 10*HSROW;
    float*  vsII = vsIP + 10*HSROW;
    float2* sAB  = reinterpret_cast<float2*>(vsII + 10*HSROW);  // [10][LW]

    const int mb = blockIdx.x;            // 0..31
    const int pl = blockIdx.y;
    const int t  = threadIdx.x;           // column / lane role varies
    const int k0 = mb << 3;

    // ---- zero the horizontal halos (10 rows x 16 floats x 4 stats) ----
    if (t < 160) {
        const int row = t >> 4, h = t & 15;
        const int idx = row*HSROW + (h < 8 ? h : 256 + h);   // 0..7 | 264..271
        vsI[idx] = 0.f; vsP[idx] = 0.f; vsIP[idx] = 0.f; vsII[idx] = 0.f;
    }

    // ---- Stage V: vertical sliding window on column t ----
    {
        const float* __restrict__ Ic = I + pl*PLANE + t;
        const float* __restrict__ Pc = p + pl*PLANE + t;

        int rcur = max(k0 - 1, 0);
        float sI = 0.f, sP = 0.f, sIP = 0.f, sII = 0.f;
        #pragma unroll
        for (int dy = -R; dy <= R; dy++) {
            const int y = rcur + dy;      // y <= 255 always (rcur <= 247)
            if (y >= 0) {
                const float vi = Ic[y*LW], vp = Pc[y*LW];
                sI += vi; sP += vp; sIP += vi*vp; sII += vi*vi;
            }
        }

        #pragma unroll
        for (int j = 0; j < 10; j++) {
            const int target = min(max(k0 - 1 + j, 0), LH - 1);
            if (target != rcur) {
                const int ya = rcur + R + 1;
                if (ya <= LH - 1) {
                    const float vi = Ic[ya*LW], vp = Pc[ya*LW];
                    sI += vi; sP += vp; sIP += vi*vp; sII += vi*vi;
                }
                const int ys = rcur - R;
                if (ys >= 0) {
                    const float vi = Ic[ys*LW], vp = Pc[ys*LW];
                    sI -= vi; sP -= vp; sIP -= vi*vp; sII -= vi*vi;
                }
                rcur = target;
            }
            const int o = j*HSROW + 8 + t;
            vsI[o] = sI; vsP[o] = sP; vsIP[o] = sIP; vsII[o] = sII;
        }
    }
    __syncthreads();

    // ---- Stage H: horizontal 17-tap windows + solve A,B ----
    // 640 units = 10 rows x 64 col-groups (4 cols each); ~2.5 units/thread.
    for (int u = t; u < 640; u += 256) {
        const int row = u >> 6;
        const int xb  = (u & 63) << 2;

        const int ar = min(max(k0 - 1 + row, 0), LH - 1);
        const float cy = (float)(min(ar + R, LH-1) - max(ar - R, 0) + 1);

        float wI[4], wP[4], wIP[4], wII[4];
#define HW(SRC, W)                                                              \
        {                                                                       \
            const float* b = SRC + row*HSROW + xb;                              \
            const float4 q0 = *reinterpret_cast<const float4*>(b);              \
            const float4 q1 = *reinterpret_cast<const float4*>(b + 4);          \
            const float4 q2 = *reinterpret_cast<const float4*>(b + 8);          \
            const float4 q3 = *reinterpret_cast<const float4*>(b + 12);         \
            const float4 q4 = *reinterpret_cast<const float4*>(b + 16);         \
            W[0] = q0.x+q0.y+q0.z+q0.w + q1.x+q1.y+q1.z+q1.w                    \
                 + q2.x+q2.y+q2.z+q2.w + q3.x+q3.y+q3.z+q3.w + q4.x;            \
            W[1] = W[0] - q0.x + q4.y;                                          \
            W[2] = W[1] - q0.y + q4.z;                                          \
            W[3] = W[2] - q0.z + q4.w;                                          \
        }
        HW(vsI,  wI)
        HW(vsP,  wP)
        HW(vsIP, wIP)
        HW(vsII, wII)
#undef HW

        #pragma unroll
        for (int cc = 0; cc < 4; cc++) {
            const int c = xb + cc;
            const float cx  = (float)(min(c + R, LW-1) - max(c - R, 0) + 1);
            const float inv = 1.0f / (cx * cy);
            const float mI = wI[cc]*inv;
            const float mP = wP[cc]*inv;
            const float A  = (wIP[cc]*inv - mI*mP) / ((wII[cc]*inv - mI*mI) + EPSF);
            sAB[row*LW + c] = make_float2(A, mP - A*mI);
        }
    }
    __syncthreads();

    // ---- Stage A: upsample + apply ----
    const int xm = max(t - 1, 0);
    const int xp = min(t + 1, LW - 1);
    const int base = ((pl << 10) + (mb << 5)) * 1024 + (t << 2);

    #pragma unroll
    for (int i4 = 0; i4 < 8; i4++) {
        const float2 um = sAB[ i4   *LW + xm], u0 = sAB[ i4   *LW + t], up = sAB[ i4   *LW + xp];
        const float2 vm = sAB[(i4+1)*LW + xm], v0 = sAB[(i4+1)*LW + t], vp = sAB[(i4+1)*LW + xp];
        const float2 wm = sAB[(i4+2)*LW + xm], w0 = sAB[(i4+2)*LW + t], wp = sAB[(i4+2)*LW + xp];

        float uA[4], uB[4], vA[4], vB[4], wA[4], wB[4];
        uA[0] = 0.375f*um.x + 0.625f*u0.x;  uB[0] = 0.375f*um.y + 0.625f*u0.y;
        uA[1] = 0.125f*um.x + 0.875f*u0.x;  uB[1] = 0.125f*um.y + 0.875f*u0.y;
        uA[2] = 0.875f*u0.x + 0.125f*up.x;  uB[2] = 0.875f*u0.y + 0.125f*up.y;
        uA[3] = 0.625f*u0.x + 0.375f*up.x;  uB[3] = 0.625f*u0.y + 0.375f*up.y;
        vA[0] = 0.375f*vm.x + 0.625f*v0.x;  vB[0] = 0.375f*vm.y + 0.625f*v0.y;
        vA[1] = 0.125f*vm.x + 0.875f*v0.x;  vB[1] = 0.125f*vm.y + 0.875f*v0.y;
        vA[2] = 0.875f*v0.x + 0.125f*vp.x;  vB[2] = 0.875f*v0.y + 0.125f*vp.y;
        vA[3] = 0.625f*v0.x + 0.375f*vp.x;  vB[3] = 0.625f*v0.y + 0.375f*vp.y;
        wA[0] = 0.375f*wm.x + 0.625f*w0.x;  wB[0] = 0.375f*wm.y + 0.625f*w0.y;
        wA[1] = 0.125f*wm.x + 0.875f*w0.x;  wB[1] = 0.125f*wm.y + 0.875f*w0.y;
        wA[2] = 0.875f*w0.x + 0.125f*wp.x;  wB[2] = 0.875f*w0.y + 0.125f*wp.y;
        wA[3] = 0.625f*w0.x + 0.375f*wp.x;  wB[3] = 0.625f*w0.y + 0.375f*wp.y;

        const int qbase = base + (i4 << 2) * 1024;
        const float4 g0 = __ldcs(reinterpret_cast<const float4*>(Ihr + qbase));
        const float4 g1 = __ldcs(reinterpret_cast<const float4*>(Ihr + qbase + 1024));
        const float4 g2 = __ldcs(reinterpret_cast<const float4*>(Ihr + qbase + 2048));
        const float4 g3 = __ldcs(reinterpret_cast<const float4*>(Ihr + qbase + 3072));

        float4 o0, o1, o2, o3;
        o0.x = (0.375f*uA[0]+0.625f*vA[0])*g0.x + (0.375f*uB[0]+0.625f*vB[0]);
        o0.y = (0.375f*uA[1]+0.625f*vA[1])*g0.y + (0.375f*uB[1]+0.625f*vB[1]);
        o0.z = (0.375f*uA[2]+0.625f*vA[2])*g0.z + (0.375f*uB[2]+0.625f*vB[2]);
        o0.w = (0.375f*uA[3]+0.625f*vA[3])*g0.w + (0.375f*uB[3]+0.625f*vB[3]);

        o1.x = (0.125f*uA[0]+0.875f*vA[0])*g1.x + (0.125f*uB[0]+0.875f*vB[0]);
        o1.y = (0.125f*uA[1]+0.875f*vA[1])*g1.y + (0.125f*uB[1]+0.875f*vB[1]);
        o1.z = (0.125f*uA[2]+0.875f*vA[2])*g1.z + (0.125f*uB[2]+0.875f*vB[2]);
        o1.w = (0.125f*uA[3]+0.875f*vA[3])*g1.w + (0.125f*uB[3]+0.875f*vB[3]);

        o2.x = (0.875f*vA[0]+0.125f*wA[0])*g2.x + (0.875f*vB[0]+0.125f*wB[0]);
        o2.y = (0.875f*vA[1]+0.125f*wA[1])*g2.y + (0.875f*vB[1]+0.125f*wB[1]);
        o2.z = (0.875f*vA[2]+0.125f*wA[2])*g2.z + (0.875f*vB[2]+0.125f*wB[2]);
        o2.w = (0.875f*vA[3]+0.125f*wA[3])*g2.w + (0.875f*vB[3]+0.125f*wB[3]);

        o3.x = (0.625f*vA[0]+0.375f*wA[0])*g3.x + (0.625f*vB[0]+0.375f*wB[0]);
        o3.y = (0.625f*vA[1]+0.375f*wA[1])*g3.y + (0.625f*vB[1]+0.375f*wB[1]);
        o3.z = (0.625f*vA[2]+0.375f*wA[2])*g3.z + (0.625f*vB[2]+0.375f*wB[2]);
        o3.w = (0.625f*vA[3]+0.375f*wA[3])*g3.w + (0.625f*vB[3]+0.375f*wB[3]);

        __stcs(reinterpret_cast<float4*>(out + qbase),        o0);
        __stcs(reinterpret_cast<float4*>(out + qbase + 1024), o1);
        __stcs(reinterpret_cast<float4*>(out + qbase + 2048), o2);
        __stcs(reinterpret_cast<float4*>(out + qbase + 3072), o3);
    }
}

// ---------------------------------------------------------------------------
extern "C" void kernel_launch(void* const* d_in, const int* in_sizes, int n_in,
                              void* d_out, int out_size)
{
    const float* p_lr = (const float*)d_in[0];
    const float* I_lr = (const float*)d_in[1];
    const float* I_hr = (const float*)d_in[2];
    float* out = (float*)d_out;

    cudaFuncSetAttribute(k_gf, cudaFuncAttributeMaxDynamicSharedMemorySize,
                         SMEM_BYTES);
    k_gf<<<dim3(LH/8, NC), 256, SMEM_BYTES>>>(p_lr, I_lr, I_hr, out);
}

// round 15
// speedup vs baseline: 2.1405x; 1.0294x over previous
#include <cuda_runtime.h>

#define NC 24
#define LH 256
#define LW 256
#define PLANE (LH*LW)
#define R 8
#define EPSF 1e-4f
#define KROWS 4                 // LR rows per block
#define AROWS (KROWS + 2)       // A/B rows needed (k0-1 .. k0+KROWS)
#define HSROW 272               // 8 zero-halo + 256 + 8 zero-halo
#define SMEM_BYTES (4*AROWS*HSROW*4 + AROWS*LW*8)   // 26112 + 12288 = 38400

// ---------------------------------------------------------------------------
// Single fused kernel. Block mb covers HR rows 16mb..16mb+15 (LR rows
// k0..k0+3, k0=4mb). Grid = (64, NC), 256 threads.
//   Stage V: per-column vertical truncated sliding window over raw I,p
//            -> AROWS vsum rows (stats I,P,IP,II) in zero-padded smem.
//   Stage H: horizontal 17-tap running-sum windows + solve -> sAB smem.
//   Stage A: x4 bilinear upsample (half-pixel, edge-clamp == jax linear)
//            fused with out = A*I_hr + B. 4 quads x 4 float4 per thread.
// ---------------------------------------------------------------------------
__global__ void __launch_bounds__(256, 5) k_gf(
    const float* __restrict__ p, const float* __restrict__ I,
    const float* __restrict__ Ihr, float* __restrict__ out)
{
    extern __shared__ float sm[];
    float*  vsI  = sm;                    // [AROWS][HSROW]
    float*  vsP  = vsI  + AROWS*HSROW;
    float*  vsIP = vsP  + AROWS*HSROW;
    float*  vsII = vsIP + AROWS*HSROW;
    float2* sAB  = reinterpret_cast<float2*>(vsII + AROWS*HSROW);  // [AROWS][LW]

    const int mb = blockIdx.x;            // 0..63
    const int pl = blockIdx.y;
    const int t  = threadIdx.x;
    const int k0 = mb << 2;

    // ---- zero the horizontal halos (AROWS rows x 16 floats x 4 stats) ----
    if (t < AROWS*16) {
        const int row = t >> 4, h = t & 15;
        const int idx = row*HSROW + (h < 8 ? h : 256 + h);   // 0..7 | 264..271
        vsI[idx] = 0.f; vsP[idx] = 0.f; vsIP[idx] = 0.f; vsII[idx] = 0.f;
    }

    // ---- Stage V: vertical sliding window on column t ----
    {
        const float* __restrict__ Ic = I + pl*PLANE + t;
        const float* __restrict__ Pc = p + pl*PLANE + t;

        int rcur = max(k0 - 1, 0);
        float sI = 0.f, sP = 0.f, sIP = 0.f, sII = 0.f;
        #pragma unroll
        for (int dy = -R; dy <= R; dy++) {
            const int y = rcur + dy;
            if (y >= 0 && y <= LH - 1) {
                const float vi = Ic[y*LW], vp = Pc[y*LW];
                sI += vi; sP += vp; sIP += vi*vp; sII += vi*vi;
            }
        }

        #pragma unroll
        for (int j = 0; j < AROWS; j++) {
            const int target = min(max(k0 - 1 + j, 0), LH - 1);
            if (target != rcur) {
                const int ya = rcur + R + 1;
                if (ya <= LH - 1) {
                    const float vi = Ic[ya*LW], vp = Pc[ya*LW];
                    sI += vi; sP += vp; sIP += vi*vp; sII += vi*vi;
                }
                const int ys = rcur - R;
                if (ys >= 0) {
                    const float vi = Ic[ys*LW], vp = Pc[ys*LW];
                    sI -= vi; sP -= vp; sIP -= vi*vp; sII -= vi*vi;
                }
                rcur = target;
            }
            const int o = j*HSROW + 8 + t;
            vsI[o] = sI; vsP[o] = sP; vsIP[o] = sIP; vsII[o] = sII;
        }
    }
    __syncthreads();

    // ---- Stage H: horizontal 17-tap windows + solve A,B ----
    // AROWS*64 = 384 units (4 cols each); 1.5 units/thread.
    for (int u = t; u < AROWS*64; u += 256) {
        const int row = u >> 6;
        const int xb  = (u & 63) << 2;

        const int ar = min(max(k0 - 1 + row, 0), LH - 1);
        const float cy = (float)(min(ar + R, LH-1) - max(ar - R, 0) + 1);

        float wI[4], wP[4], wIP[4], wII[4];
#define HW(SRC, W)                                                              \
        {                                                                       \
            const float* b = SRC + row*HSROW + xb;                              \
            const float4 q0 = *reinterpret_cast<const float4*>(b);              \
            const float4 q1 = *reinterpret_cast<const float4*>(b + 4);          \
            const float4 q2 = *reinterpret_cast<const float4*>(b + 8);          \
            const float4 q3 = *reinterpret_cast<const float4*>(b + 12);         \
            const float4 q4 = *reinterpret_cast<const float4*>(b + 16);         \
            W[0] = q0.x+q0.y+q0.z+q0.w + q1.x+q1.y+q1.z+q1.w                    \
                 + q2.x+q2.y+q2.z+q2.w + q3.x+q3.y+q3.z+q3.w + q4.x;            \
            W[1] = W[0] - q0.x + q4.y;                                          \
            W[2] = W[1] - q0.y + q4.z;                                          \
            W[3] = W[2] - q0.z + q4.w;                                          \
        }
        HW(vsI,  wI)
        HW(vsP,  wP)
        HW(vsIP, wIP)
        HW(vsII, wII)
#undef HW

        #pragma unroll
        for (int cc = 0; cc < 4; cc++) {
            const int c = xb + cc;
            const float cx  = (float)(min(c + R, LW-1) - max(c - R, 0) + 1);
            const float inv = 1.0f / (cx * cy);
            const float mI = wI[cc]*inv;
            const float mP = wP[cc]*inv;
            const float A  = (wIP[cc]*inv - mI*mP) / ((wII[cc]*inv - mI*mI) + EPSF);
            sAB[row*LW + c] = make_float2(A, mP - A*mI);
        }
    }
    __syncthreads();

    // ---- Stage A: upsample + apply ----
    const int xm = max(t - 1, 0);
    const int xp = min(t + 1, LW - 1);
    const int base = ((pl << 10) + (mb << 4)) * 1024 + (t << 2);

    #pragma unroll
    for (int i4 = 0; i4 < KROWS; i4++) {
        const float2 um = sAB[ i4   *LW + xm], u0 = sAB[ i4   *LW + t], up = sAB[ i4   *LW + xp];
        const float2 vm = sAB[(i4+1)*LW + xm], v0 = sAB[(i4+1)*LW + t], vp = sAB[(i4+1)*LW + xp];
        const float2 wm = sAB[(i4+2)*LW + xm], w0 = sAB[(i4+2)*LW + t], wp = sAB[(i4+2)*LW + xp];

        float uA[4], uB[4], vA[4], vB[4], wA[4], wB[4];
        uA[0] = 0.375f*um.x + 0.625f*u0.x;  uB[0] = 0.375f*um.y + 0.625f*u0.y;
        uA[1] = 0.125f*um.x + 0.875f*u0.x;  uB[1] = 0.125f*um.y + 0.875f*u0.y;
        uA[2] = 0.875f*u0.x + 0.125f*up.x;  uB[2] = 0.875f*u0.y + 0.125f*up.y;
        uA[3] = 0.625f*u0.x + 0.375f*up.x;  uB[3] = 0.625f*u0.y + 0.375f*up.y;
        vA[0] = 0.375f*vm.x + 0.625f*v0.x;  vB[0] = 0.375f*vm.y + 0.625f*v0.y;
        vA[1] = 0.125f*vm.x + 0.875f*v0.x;  vB[1] = 0.125f*vm.y + 0.875f*v0.y;
        vA[2] = 0.875f*v0.x + 0.125f*vp.x;  vB[2] = 0.875f*v0.y + 0.125f*vp.y;
        vA[3] = 0.625f*v0.x + 0.375f*vp.x;  vB[3] = 0.625f*v0.y + 0.375f*vp.y;
        wA[0] = 0.375f*wm.x + 0.625f*w0.x;  wB[0] = 0.375f*wm.y + 0.625f*w0.y;
        wA[1] = 0.125f*wm.x + 0.875f*w0.x;  wB[1] = 0.125f*wm.y + 0.875f*w0.y;
        wA[2] = 0.875f*w0.x + 0.125f*wp.x;  wB[2] = 0.875f*w0.y + 0.125f*wp.y;
        wA[3] = 0.625f*w0.x + 0.375f*wp.x;  wB[3] = 0.625f*w0.y + 0.375f*wp.y;

        const int qbase = base + (i4 << 2) * 1024;
        const float4 g0 = __ldcs(reinterpret_cast<const float4*>(Ihr + qbase));
        const float4 g1 = __ldcs(reinterpret_cast<const float4*>(Ihr + qbase + 1024));
        const float4 g2 = __ldcs(reinterpret_cast<const float4*>(Ihr + qbase + 2048));
        const float4 g3 = __ldcs(reinterpret_cast<const float4*>(Ihr + qbase + 3072));

        float4 o0, o1, o2, o3;
        o0.x = (0.375f*uA[0]+0.625f*vA[0])*g0.x + (0.375f*uB[0]+0.625f*vB[0]);
        o0.y = (0.375f*uA[1]+0.625f*vA[1])*g0.y + (0.375f*uB[1]+0.625f*vB[1]);
        o0.z = (0.375f*uA[2]+0.625f*vA[2])*g0.z + (0.375f*uB[2]+0.625f*vB[2]);
        o0.w = (0.375f*uA[3]+0.625f*vA[3])*g0.w + (0.375f*uB[3]+0.625f*vB[3]);

        o1.x = (0.125f*uA[0]+0.875f*vA[0])*g1.x + (0.125f*uB[0]+0.875f*vB[0]);
        o1.y = (0.125f*uA[1]+0.875f*vA[1])*g1.y + (0.125f*uB[1]+0.875f*vB[1]);
        o1.z = (0.125f*uA[2]+0.875f*vA[2])*g1.z + (0.125f*uB[2]+0.875f*vB[2]);
        o1.w = (0.125f*uA[3]+0.875f*vA[3])*g1.w + (0.125f*uB[3]+0.875f*vB[3]);

        o2.x = (0.875f*vA[0]+0.125f*wA[0])*g2.x + (0.875f*vB[0]+0.125f*wB[0]);
        o2.y = (0.875f*vA[1]+0.125f*wA[1])*g2.y + (0.875f*vB[1]+0.125f*wB[1]);
        o2.z = (0.875f*vA[2]+0.125f*wA[2])*g2.z + (0.875f*vB[2]+0.125f*wB[2]);
        o2.w = (0.875f*vA[3]+0.125f*wA[3])*g2.w + (0.875f*vB[3]+0.125f*wB[3]);

        o3.x = (0.625f*vA[0]+0.375f*wA[0])*g3.x + (0.625f*vB[0]+0.375f*wB[0]);
        o3.y = (0.625f*vA[1]+0.375f*wA[1])*g3.y + (0.625f*vB[1]+0.375f*wB[1]);
        o3.z = (0.625f*vA[2]+0.375f*wA[2])*g3.z + (0.625f*vB[2]+0.375f*wB[2]);
        o3.w = (0.625f*vA[3]+0.375f*wA[3])*g3.w + (0.625f*vB[3]+0.375f*wB[3]);

        __stcs(reinterpret_cast<float4*>(out + qbase),        o0);
        __stcs(reinterpret_cast<float4*>(out + qbase + 1024), o1);
        __stcs(reinterpret_cast<float4*>(out + qbase + 2048), o2);
        __stcs(reinterpret_cast<float4*>(out + qbase + 3072), o3);
    }
}

// ---------------------------------------------------------------------------
extern "C" void kernel_launch(void* const* d_in, const int* in_sizes, int n_in,
                              void* d_out, int out_size)
{
    const float* p_lr = (const float*)d_in[0];
    const float* I_lr = (const float*)d_in[1];
    const float* I_hr = (const float*)d_in[2];
    float* out = (float*)d_out;

    cudaFuncSetAttribute(k_gf, cudaFuncAttributeMaxDynamicSharedMemorySize,
                         SMEM_BYTES);
    k_gf<<<dim3(LH/KROWS, NC), 256, SMEM_BYTES>>>(p_lr, I_lr, I_hr, out);
}